// round 11
// baseline (speedup 1.0000x reference)
#include <cuda_runtime.h>
#include <cuda_bf16.h>
#include <cstdint>

// Problem dims (fixed)
#define M_DIM 1024
#define K_DIM 4096
#define N_DIM 4096
#define QBLK  32
#define NKB   (K_DIM / QBLK)      // 128

// GEMM tiling: 64x64 CTA tile, 8 warps (32x16 warp tiles), STAGES=3, 3 CTAs/SM
#define BM 64
#define BN 64
#define BK 128                    // 128 fp8 = 128B rows (SW128), 4 quant blocks
#define STAGES 3
#define NITER (K_DIM / BK)        // 32
#define THREADS 256

// Stage smem: A(8K) | B(8K) | sx(1K) | sw(1K)
#define A_OFF   0
#define B_OFF   8192
#define SX_OFF  16384
#define SW_OFF  17408
#define STAGE_B 18432
#define SMEM_TOTAL (STAGES * STAGE_B)   // 55296 -> 3 CTAs/SM (w/ 256 thr)

// Scratch (device globals)
__device__ uint8_t g_qx[(size_t)M_DIM * K_DIM];   // 4 MB  (e4m3 palette)
__device__ uint8_t g_qw[(size_t)N_DIM * K_DIM];   // 16 MB (e4m3 palette)
__device__ float   g_sx[(size_t)NKB * M_DIM];     // [kb][m] = bm/6
__device__ float   g_sw[(size_t)NKB * N_DIM];     // [kb][n] = bm/6

// ---------------------------------------------------------------------------
// PTX helpers
// ---------------------------------------------------------------------------
__device__ __forceinline__ uint32_t smem_u32(const void* p) {
    uint32_t a;
    asm("{ .reg .u64 t; cvta.to.shared.u64 t, %1; cvt.u32.u64 %0, t; }"
        : "=r"(a) : "l"(p));
    return a;
}
#define CP_ASYNC16(dst, src) \
    asm volatile("cp.async.cg.shared.global [%0], [%1], 16;" \
                 :: "r"(dst), "l"(src) : "memory")
#define CP_COMMIT() asm volatile("cp.async.commit_group;" ::: "memory")
#define CP_WAIT(n)  asm volatile("cp.async.wait_group %0;" :: "n"(n) : "memory")

#define LDSM4(r0, r1, r2, r3, addr) \
    asm volatile("ldmatrix.sync.aligned.m8n8.x4.shared.b16 {%0,%1,%2,%3}, [%4];" \
                 : "=r"(r0), "=r"(r1), "=r"(r2), "=r"(r3) : "r"(addr))

// fp8 e4m3 MMA, K=32, fp32 accum, C = 0 (exact partial over one quant block)
#define MMA_FP8_Z(d, a, b0, b1) \
    asm volatile("mma.sync.aligned.m16n8k32.row.col.f32.e4m3.e4m3.f32 " \
        "{%0,%1,%2,%3},{%4,%5,%6,%7},{%8,%9},{%10,%10,%10,%10};" \
        : "=f"((d)[0]), "=f"((d)[1]), "=f"((d)[2]), "=f"((d)[3]) \
        : "r"((a)[0]), "r"((a)[1]), "r"((a)[2]), "r"((a)[3]), \
          "r"(b0), "r"(b1), "f"(0.0f))

// packed f32x2 ops
__device__ __forceinline__ unsigned long long pk2(float lo, float hi) {
    unsigned long long d;
    asm("mov.b64 %0, {%1, %2};" : "=l"(d) : "f"(lo), "f"(hi));
    return d;
}
__device__ __forceinline__ unsigned long long pmul2(unsigned long long a,
                                                    unsigned long long b) {
    unsigned long long d;
    asm("mul.rn.f32x2 %0, %1, %2;" : "=l"(d) : "l"(a), "l"(b));
    return d;
}
__device__ __forceinline__ void pfma2(unsigned long long& acc,
                                      unsigned long long a,
                                      unsigned long long b) {
    asm("fma.rn.f32x2 %0, %1, %2, %0;" : "+l"(acc) : "l"(a), "l"(b));
}

__device__ __forceinline__ uint32_t swz128(uint32_t off) {
    return off ^ ((off >> 3) & 0x70);
}

// ---------------------------------------------------------------------------
// Quantize v5 (fused): ceil-based EXACT snap (argmin tie-to-lower preserved).
// ---------------------------------------------------------------------------
__device__ __forceinline__ float snap1(float v, float r6) {
    float su = fabsf(v) * r6;
    float pl = ceilf(fmaf(su, 2.0f, -0.5f)) * 0.5f;
    float ph = fminf(ceilf(su - 0.5f), 4.0f);
    float p  = su < 2.0f ? pl : ph;
    p = su > 5.0f ? 6.0f : p;
    return copysignf(p, v);
}
__device__ __forceinline__ uint32_t pack4_e4m3(float v0, float v1,
                                               float v2, float v3) {
    uint16_t lo, hi;
    asm("cvt.rn.satfinite.e4m3x2.f32 %0, %1, %2;" : "=h"(lo) : "f"(v1), "f"(v0));
    asm("cvt.rn.satfinite.e4m3x2.f32 %0, %1, %2;" : "=h"(hi) : "f"(v3), "f"(v2));
    return (uint32_t)lo | ((uint32_t)hi << 16);
}

#define XTHREADS ((M_DIM * (size_t)K_DIM) / 16)   // 262144

__global__ __launch_bounds__(256)
void quant_fused_kernel(const float* __restrict__ x,
                        const float* __restrict__ w,
                        uint8_t* __restrict__ qx,
                        uint8_t* __restrict__ qw,
                        float* __restrict__ sx,
                        float* __restrict__ sw) {
    const size_t gt = blockIdx.x * 256 + threadIdx.x;

    const float* src;
    uint8_t* dst;
    float* sdst;
    int rows;
    size_t e0;
    if (gt < XTHREADS) {
        src = x;  dst = qx;  sdst = sx;  rows = M_DIM;  e0 = gt * 16;
    } else {
        src = w;  dst = qw;  sdst = sw;  rows = N_DIM;  e0 = (gt - XTHREADS) * 16;
    }

    float4 v[4];
    #pragma unroll
    for (int i = 0; i < 4; i++) v[i] = *(const float4*)(src + e0 + i * 4);

    float a = 0.0f;
    #pragma unroll
    for (int i = 0; i < 4; i++) {
        a = fmaxf(a, fmaxf(fmaxf(fabsf(v[i].x), fabsf(v[i].y)),
                           fmaxf(fabsf(v[i].z), fabsf(v[i].w))));
    }
    a = fmaxf(a, __shfl_xor_sync(0xffffffffu, a, 1));
    float bm = fmaxf(a, 1e-12f);
    float r6 = 6.0f / bm;

    uint4 pk;
    pk.x = pack4_e4m3(snap1(v[0].x, r6), snap1(v[0].y, r6),
                      snap1(v[0].z, r6), snap1(v[0].w, r6));
    pk.y = pack4_e4m3(snap1(v[1].x, r6), snap1(v[1].y, r6),
                      snap1(v[1].z, r6), snap1(v[1].w, r6));
    pk.z = pack4_e4m3(snap1(v[2].x, r6), snap1(v[2].y, r6),
                      snap1(v[2].z, r6), snap1(v[2].w, r6));
    pk.w = pack4_e4m3(snap1(v[3].x, r6), snap1(v[3].y, r6),
                      snap1(v[3].z, r6), snap1(v[3].w, r6));
    *(uint4*)(dst + e0) = pk;

    if ((threadIdx.x & 1) == 0) {
        int row = (int)(e0 / K_DIM);
        int kb  = (int)((e0 % K_DIM) / QBLK);
        sdst[(size_t)kb * rows + row] = bm / 6.0f;
    }
}

// ---------------------------------------------------------------------------
// FP8 block-scaled GEMM: 64x64 CTA, 8 warps of 32x16 tiles (2m x 4n grid),
// STAGES=3 cp.async pipeline, 3 CTAs/SM -> 24 warps/SM.
// C[m,n] = sum_kb MMA_k32(qx,qw) * sx[m,kb]*sw[n,kb]
// ---------------------------------------------------------------------------
__global__ __launch_bounds__(THREADS, 3)
void gemm_fp8(const uint8_t* __restrict__ A,   // [M,K] e4m3
              const uint8_t* __restrict__ B,   // [N,K] e4m3
              const float* __restrict__ SX,    // [NKB][M]
              const float* __restrict__ SW,    // [NKB][N]
              float* __restrict__ C) {
    extern __shared__ __align__(1024) char smem[];
    const uint32_t sb = smem_u32(smem);
    const int tid  = threadIdx.x;
    const int wid  = tid >> 5;
    const int lane = tid & 31;
    const int m0   = (wid >> 2) * 32;   // 2 m-groups
    const int n0   = (wid & 3) * 16;    // 4 n-groups
    const int bm0  = blockIdx.y * BM;
    const int bn0  = blockIdx.x * BN;

    auto load_stage = [&](int buf, int it) {
        const uint32_t st = sb + buf * STAGE_B;
        const int k0 = it * BK;
        #pragma unroll
        for (int i = 0; i < 2; i++) {           // A: 64 rows x 8 chunks = 512
            int c = tid + i * THREADS;
            int row = c >> 3, k16 = c & 7;
            const uint8_t* gA = A + (size_t)(bm0 + row) * K_DIM + k0 + k16 * 16;
            CP_ASYNC16(st + A_OFF + swz128(row * 128 + k16 * 16), gA);
        }
        #pragma unroll
        for (int i = 0; i < 2; i++) {           // B: 64 rows x 8 chunks = 512
            int c = tid + i * THREADS;
            int row = c >> 3, k16 = c & 7;
            const uint8_t* gB = B + (size_t)(bn0 + row) * K_DIM + k0 + k16 * 16;
            CP_ASYNC16(st + B_OFF + swz128(row * 128 + k16 * 16), gB);
        }
        if (tid < 128) {                        // scales: 128 x 16B chunks
            int half = tid >> 6;                // 0 = sx, 1 = sw
            int cc   = tid & 63;
            int kbl  = cc >> 4;                 // 0..3
            int qq   = cc & 15;
            int kb   = it * 4 + kbl;
            if (half == 0) {
                const float* g = SX + (size_t)kb * M_DIM + bm0 + qq * 4;
                CP_ASYNC16(st + SX_OFF + kbl * 256 + qq * 16, g);
            } else {
                const float* g = SW + (size_t)kb * N_DIM + bn0 + qq * 4;
                CP_ASYNC16(st + SW_OFF + kbl * 256 + qq * 16, g);
            }
        }
    };

    // packed fp32 accumulators: acc2[tm][tn][h] = (c_even, c_odd)
    unsigned long long acc2[2][2][2];
    #pragma unroll
    for (int i = 0; i < 2; i++)
        #pragma unroll
        for (int j = 0; j < 2; j++) {
            acc2[i][j][0] = 0ull; acc2[i][j][1] = 0ull;
        }

    #pragma unroll
    for (int s = 0; s < STAGES - 1; s++) {
        load_stage(s, s);
        CP_COMMIT();
    }

    // hoisted, loop-invariant swizzled ldmatrix offsets
    const int r       = lane & 7;
    const int sel     = lane >> 3;
    const int selRow  = (sel & 1) * 8;
    const int selByte = (sel >> 1) * 16;
    const int qrow    = lane >> 2;   // 0..7
    const int qcol    = (lane & 3) * 2;

    uint32_t offA[4][2], offB[4];
    #pragma unroll
    for (int kb = 0; kb < 4; kb++) {
        const int kbyte = kb * 32 + selByte;
        #pragma unroll
        for (int tm = 0; tm < 2; tm++)
            offA[kb][tm] = A_OFF +
                swz128((m0 + tm * 16 + r + selRow) * 128 + kbyte);
        offB[kb] = B_OFF + swz128((n0 + r + selRow) * 128 + kbyte);
    }
    const int sxBase = (m0 + qrow) * 4;         // + 64*tm + 32*h + kb*256
    const int swBase = (n0 + qcol) * 4;         // + 32*tn + kb*256

    int cbuf = 0;                    // compute buffer cursor
    int lbuf = STAGES - 1;           // next load buffer cursor

    for (int it = 0; it < NITER; it++) {
        CP_WAIT(STAGES - 2);
        __syncthreads();

        if (it + STAGES - 1 < NITER)
            load_stage(lbuf, it + STAGES - 1);
        CP_COMMIT();
        lbuf = (lbuf == STAGES - 1) ? 0 : lbuf + 1;

        const uint32_t su = sb + cbuf * STAGE_B;
        const char* sxS = smem + cbuf * STAGE_B + SX_OFF;
        const char* swS = smem + cbuf * STAGE_B + SW_OFF;
        cbuf = (cbuf == STAGES - 1) ? 0 : cbuf + 1;

        #pragma unroll
        for (int kb = 0; kb < 4; kb++) {
            uint32_t a[2][4], b[4];
            #pragma unroll
            for (int tm = 0; tm < 2; tm++)
                LDSM4(a[tm][0], a[tm][1], a[tm][2], a[tm][3], su + offA[kb][tm]);
            LDSM4(b[0], b[1], b[2], b[3], su + offB[kb]);

            // scales for this quant block
            unsigned long long sxd[2][2];
            #pragma unroll
            for (int tm = 0; tm < 2; tm++)
                #pragma unroll
                for (int h = 0; h < 2; h++) {
                    float sx = *(const float*)(sxS + kb * 256 + sxBase +
                                               tm * 64 + h * 32);
                    sxd[tm][h] = pk2(sx, sx);
                }
            unsigned long long swp[2];
            #pragma unroll
            for (int tn = 0; tn < 2; tn++)
                swp[tn] = *(const unsigned long long*)(swS + kb * 256 +
                                                       swBase + tn * 32);

            // MMA + scaled accumulation
            #pragma unroll
            for (int tm = 0; tm < 2; tm++) {
                float p[4], q[4];
                MMA_FP8_Z(p, a[tm], b[0], b[2]);   // tn = 0 (n0..n0+7)
                MMA_FP8_Z(q, a[tm], b[1], b[3]);   // tn = 1 (n0+8..n0+15)
                pfma2(acc2[tm][0][0], pk2(p[0], p[1]), pmul2(sxd[tm][0], swp[0]));
                pfma2(acc2[tm][0][1], pk2(p[2], p[3]), pmul2(sxd[tm][1], swp[0]));
                pfma2(acc2[tm][1][0], pk2(q[0], q[1]), pmul2(sxd[tm][0], swp[1]));
                pfma2(acc2[tm][1][1], pk2(q[2], q[3]), pmul2(sxd[tm][1], swp[1]));
            }
        }
    }

    // epilogue: 8-byte packed stores
    #pragma unroll
    for (int tm = 0; tm < 2; tm++)
        #pragma unroll
        for (int h = 0; h < 2; h++) {
            int row = bm0 + m0 + tm * 16 + qrow + 8 * h;
            #pragma unroll
            for (int tn = 0; tn < 2; tn++) {
                unsigned long long v = acc2[tm][tn][h];
                *(unsigned long long*)(C + (size_t)row * N_DIM +
                                       bn0 + n0 + tn * 8 + qcol) = v;
            }
        }
}

// ---------------------------------------------------------------------------
extern "C" void kernel_launch(void* const* d_in, const int* in_sizes, int n_in,
                              void* d_out, int out_size) {
    (void)n_in; (void)in_sizes; (void)out_size;
    const float* x = (const float*)d_in[0];   // [M, K]
    const float* w = (const float*)d_in[1];   // [N, K]
    float* out = (float*)d_out;               // [M, N]

    uint8_t *qx = nullptr, *qw = nullptr;
    float *sx = nullptr, *sw = nullptr;
    cudaGetSymbolAddress((void**)&qx, g_qx);
    cudaGetSymbolAddress((void**)&qw, g_qw);
    cudaGetSymbolAddress((void**)&sx, g_sx);
    cudaGetSymbolAddress((void**)&sw, g_sw);

    // fused quant: x (1024 CTAs) + w (4096 CTAs) in one launch
    const int total_ctas = (int)(((M_DIM + N_DIM) * (size_t)K_DIM) / 16 / 256);
    quant_fused_kernel<<<total_ctas, 256>>>(x, w, qx, qw, sx, sw);

    cudaFuncSetAttribute(gemm_fp8,
                         cudaFuncAttributeMaxDynamicSharedMemorySize,
                         SMEM_TOTAL);
    dim3 grid(N_DIM / BN, M_DIM / BM);        // (64, 16) = 1024 CTAs
    gemm_fp8<<<grid, THREADS, SMEM_TOTAL>>>(qx, qw, sx, sw, out);
}

// round 12
// speedup vs baseline: 1.1279x; 1.1279x over previous
#include <cuda_runtime.h>
#include <cuda_bf16.h>
#include <cstdint>

// Problem dims (fixed)
#define M_DIM 1024
#define K_DIM 4096
#define N_DIM 4096
#define QBLK  32
#define NKB   (K_DIM / QBLK)      // 128

// GEMM tiling: 64x64 CTA, 4 warps of 32x32, STAGES=4, 3 CTAs/SM
#define BM 64
#define BN 64
#define BK 128                    // 128 fp8 = 128B rows (SW128), 4 quant blocks
#define STAGES 4
#define NITER (K_DIM / BK)        // 32
#define THREADS 128

// Stage smem: A(8K) | B(8K) | sx(1K) | sw(1K)
#define A_OFF   0
#define B_OFF   8192
#define SX_OFF  16384
#define SW_OFF  17408
#define STAGE_B 18432
#define SMEM_TOTAL (STAGES * STAGE_B)   // 73728 -> 3 CTAs/SM

// Scratch (device globals)
__device__ uint8_t g_qx[(size_t)M_DIM * K_DIM];   // 4 MB  (e4m3 palette)
__device__ uint8_t g_qw[(size_t)N_DIM * K_DIM];   // 16 MB (e4m3 palette)
__device__ float   g_sx[(size_t)NKB * M_DIM];     // [kb][m] = bm/6
__device__ float   g_sw[(size_t)NKB * N_DIM];     // [kb][n] = bm/6

// ---------------------------------------------------------------------------
// PTX helpers
// ---------------------------------------------------------------------------
__device__ __forceinline__ uint32_t smem_u32(const void* p) {
    uint32_t a;
    asm("{ .reg .u64 t; cvta.to.shared.u64 t, %1; cvt.u32.u64 %0, t; }"
        : "=r"(a) : "l"(p));
    return a;
}
#define CP_ASYNC16(dst, src) \
    asm volatile("cp.async.cg.shared.global [%0], [%1], 16;" \
                 :: "r"(dst), "l"(src) : "memory")
#define CP_COMMIT() asm volatile("cp.async.commit_group;" ::: "memory")
#define CP_WAIT(n)  asm volatile("cp.async.wait_group %0;" :: "n"(n) : "memory")

#define LDSM4(r0, r1, r2, r3, addr) \
    asm volatile("ldmatrix.sync.aligned.m8n8.x4.shared.b16 {%0,%1,%2,%3}, [%4];" \
                 : "=r"(r0), "=r"(r1), "=r"(r2), "=r"(r3) : "r"(addr))

// fp8 e4m3 MMA, K=32, fp32 accum, C = 0 (exact partial over one quant block)
#define MMA_FP8_Z(d, a, b0, b1) \
    asm volatile("mma.sync.aligned.m16n8k32.row.col.f32.e4m3.e4m3.f32 " \
        "{%0,%1,%2,%3},{%4,%5,%6,%7},{%8,%9},{%10,%10,%10,%10};" \
        : "=f"((d)[0]), "=f"((d)[1]), "=f"((d)[2]), "=f"((d)[3]) \
        : "r"((a)[0]), "r"((a)[1]), "r"((a)[2]), "r"((a)[3]), \
          "r"(b0), "r"(b1), "f"(0.0f))

// packed f32x2 ops
__device__ __forceinline__ unsigned long long pk2(float lo, float hi) {
    unsigned long long d;
    asm("mov.b64 %0, {%1, %2};" : "=l"(d) : "f"(lo), "f"(hi));
    return d;
}
__device__ __forceinline__ unsigned long long pmul2(unsigned long long a,
                                                    unsigned long long b) {
    unsigned long long d;
    asm("mul.rn.f32x2 %0, %1, %2;" : "=l"(d) : "l"(a), "l"(b));
    return d;
}
__device__ __forceinline__ void pfma2(unsigned long long& acc,
                                      unsigned long long a,
                                      unsigned long long b) {
    asm("fma.rn.f32x2 %0, %1, %2, %0;" : "+l"(acc) : "l"(a), "l"(b));
}

__device__ __forceinline__ uint32_t swz128(uint32_t off) {
    return off ^ ((off >> 3) & 0x70);
}

// ---------------------------------------------------------------------------
// Quantize v5 (fused): ceil-based EXACT snap (argmin tie-to-lower preserved).
// ---------------------------------------------------------------------------
__device__ __forceinline__ float snap1(float v, float r6) {
    float su = fabsf(v) * r6;
    float pl = ceilf(fmaf(su, 2.0f, -0.5f)) * 0.5f;
    float ph = fminf(ceilf(su - 0.5f), 4.0f);
    float p  = su < 2.0f ? pl : ph;
    p = su > 5.0f ? 6.0f : p;
    return copysignf(p, v);
}
__device__ __forceinline__ uint32_t pack4_e4m3(float v0, float v1,
                                               float v2, float v3) {
    uint16_t lo, hi;
    asm("cvt.rn.satfinite.e4m3x2.f32 %0, %1, %2;" : "=h"(lo) : "f"(v1), "f"(v0));
    asm("cvt.rn.satfinite.e4m3x2.f32 %0, %1, %2;" : "=h"(hi) : "f"(v3), "f"(v2));
    return (uint32_t)lo | ((uint32_t)hi << 16);
}

#define XTHREADS ((M_DIM * (size_t)K_DIM) / 16)   // 262144

__global__ __launch_bounds__(256)
void quant_fused_kernel(const float* __restrict__ x,
                        const float* __restrict__ w,
                        uint8_t* __restrict__ qx,
                        uint8_t* __restrict__ qw,
                        float* __restrict__ sx,
                        float* __restrict__ sw) {
    const size_t gt = blockIdx.x * 256 + threadIdx.x;

    const float* src;
    uint8_t* dst;
    float* sdst;
    int rows;
    size_t e0;
    if (gt < XTHREADS) {
        src = x;  dst = qx;  sdst = sx;  rows = M_DIM;  e0 = gt * 16;
    } else {
        src = w;  dst = qw;  sdst = sw;  rows = N_DIM;  e0 = (gt - XTHREADS) * 16;
    }

    float4 v[4];
    #pragma unroll
    for (int i = 0; i < 4; i++) v[i] = *(const float4*)(src + e0 + i * 4);

    float a = 0.0f;
    #pragma unroll
    for (int i = 0; i < 4; i++) {
        a = fmaxf(a, fmaxf(fmaxf(fabsf(v[i].x), fabsf(v[i].y)),
                           fmaxf(fabsf(v[i].z), fabsf(v[i].w))));
    }
    a = fmaxf(a, __shfl_xor_sync(0xffffffffu, a, 1));
    float bm = fmaxf(a, 1e-12f);
    float r6 = 6.0f / bm;

    uint4 pk;
    pk.x = pack4_e4m3(snap1(v[0].x, r6), snap1(v[0].y, r6),
                      snap1(v[0].z, r6), snap1(v[0].w, r6));
    pk.y = pack4_e4m3(snap1(v[1].x, r6), snap1(v[1].y, r6),
                      snap1(v[1].z, r6), snap1(v[1].w, r6));
    pk.z = pack4_e4m3(snap1(v[2].x, r6), snap1(v[2].y, r6),
                      snap1(v[2].z, r6), snap1(v[2].w, r6));
    pk.w = pack4_e4m3(snap1(v[3].x, r6), snap1(v[3].y, r6),
                      snap1(v[3].z, r6), snap1(v[3].w, r6));
    *(uint4*)(dst + e0) = pk;

    if ((threadIdx.x & 1) == 0) {
        int row = (int)(e0 / K_DIM);
        int kb  = (int)((e0 % K_DIM) / QBLK);
        sdst[(size_t)kb * rows + row] = bm / 6.0f;
    }
}

// ---------------------------------------------------------------------------
// FP8 block-scaled GEMM: 64x64 CTA, 4 warps of 32x32, STAGES=4, 3 CTAs/SM.
// Hoisted loader pointers + whole-stage fragment prefetch (16 ldsm upfront).
// C[m,n] = sum_kb MMA_k32(qx,qw) * sx[m,kb]*sw[n,kb]
// ---------------------------------------------------------------------------
__global__ __launch_bounds__(THREADS, 3)
void gemm_fp8(const uint8_t* __restrict__ A,   // [M,K] e4m3
              const uint8_t* __restrict__ B,   // [N,K] e4m3
              const float* __restrict__ SX,    // [NKB][M]
              const float* __restrict__ SW,    // [NKB][N]
              float* __restrict__ C) {
    extern __shared__ __align__(1024) char smem[];
    const uint32_t sb = smem_u32(smem);
    const int tid  = threadIdx.x;
    const int wid  = tid >> 5;
    const int lane = tid & 31;
    const int m0   = (wid >> 1) * 32;
    const int n0   = (wid & 1) * 32;
    const int bm0  = blockIdx.y * BM;
    const int bn0  = blockIdx.x * BN;

    // ---- hoisted loader state: 8 tile pointers + 1 scale pointer ----
    const uint8_t* pA[4];
    const uint8_t* pB[4];
    uint32_t dA[4], dB[4];
    #pragma unroll
    for (int i = 0; i < 4; i++) {
        int c = tid + i * THREADS;              // 0..511
        int row = c >> 3, k16 = c & 7;
        pA[i] = A + (size_t)(bm0 + row) * K_DIM + k16 * 16;
        pB[i] = B + (size_t)(bn0 + row) * K_DIM + k16 * 16;
        uint32_t d = swz128(row * 128 + k16 * 16);
        dA[i] = A_OFF + d;
        dB[i] = B_OFF + d;
    }
    const int sHalf = tid >> 6;                 // 0 = sx, 1 = sw
    const int sCc   = tid & 63;
    const int sKbl  = sCc >> 4;
    const int sQq   = sCc & 15;
    const float* pS;
    uint32_t dS;
    size_t sAdv;
    if (sHalf == 0) {
        pS   = SX + (size_t)sKbl * M_DIM + bm0 + sQq * 4;
        dS   = SX_OFF + sKbl * 256 + sQq * 16;
        sAdv = (size_t)4 * M_DIM * sizeof(float);
    } else {
        pS   = SW + (size_t)sKbl * N_DIM + bn0 + sQq * 4;
        dS   = SW_OFF + sKbl * 256 + sQq * 16;
        sAdv = (size_t)4 * N_DIM * sizeof(float);
    }

    auto load_stage = [&](int buf) {
        const uint32_t st = sb + buf * STAGE_B;
        #pragma unroll
        for (int i = 0; i < 4; i++) {
            CP_ASYNC16(st + dA[i], pA[i]);  pA[i] += BK;
        }
        #pragma unroll
        for (int i = 0; i < 4; i++) {
            CP_ASYNC16(st + dB[i], pB[i]);  pB[i] += BK;
        }
        CP_ASYNC16(st + dS, pS);
        pS = (const float*)((const char*)pS + sAdv);
    };

    // packed fp32 accumulators: acc2[tm][tn][h] = (c_even, c_odd)
    unsigned long long acc2[2][4][2];
    #pragma unroll
    for (int i = 0; i < 2; i++)
        #pragma unroll
        for (int j = 0; j < 4; j++) {
            acc2[i][j][0] = 0ull; acc2[i][j][1] = 0ull;
        }

    #pragma unroll
    for (int s = 0; s < STAGES - 1; s++) {
        load_stage(s);
        CP_COMMIT();
    }

    // hoisted ldsm offsets
    const int r       = lane & 7;
    const int sel     = lane >> 3;
    const int selRow  = (sel & 1) * 8;
    const int selByte = (sel >> 1) * 16;
    const int qrow    = lane >> 2;   // 0..7
    const int qcol    = (lane & 3) * 2;

    uint32_t offA[4][2], offB[4][2];
    #pragma unroll
    for (int kb = 0; kb < 4; kb++) {
        const int kbyte = kb * 32 + selByte;
        #pragma unroll
        for (int tm = 0; tm < 2; tm++)
            offA[kb][tm] = A_OFF +
                swz128((m0 + tm * 16 + r + selRow) * 128 + kbyte);
        #pragma unroll
        for (int g = 0; g < 2; g++)
            offB[kb][g] = B_OFF +
                swz128((n0 + g * 16 + r + selRow) * 128 + kbyte);
    }
    const int sxBase = (m0 + qrow) * 4;         // + 64*tm + 32*h + kb*256
    const int swBase = (n0 + qcol) * 4;         // + 32*tn + kb*256

    for (int it = 0; it < NITER; it++) {
        CP_WAIT(STAGES - 2);
        __syncthreads();

        if (it + STAGES - 1 < NITER)
            load_stage((it + STAGES - 1) & (STAGES - 1));
        CP_COMMIT();

        const int buf = it & (STAGES - 1);
        const uint32_t su = sb + buf * STAGE_B;
        const char* sxS = smem + buf * STAGE_B + SX_OFF;
        const char* swS = smem + buf * STAGE_B + SW_OFF;

        // whole-stage fragment prefetch: 16 ldsm back-to-back
        uint32_t a[4][2][4], b[4][2][4];
        #pragma unroll
        for (int kb = 0; kb < 4; kb++) {
            LDSM4(a[kb][0][0], a[kb][0][1], a[kb][0][2], a[kb][0][3],
                  su + offA[kb][0]);
            LDSM4(a[kb][1][0], a[kb][1][1], a[kb][1][2], a[kb][1][3],
                  su + offA[kb][1]);
            LDSM4(b[kb][0][0], b[kb][0][1], b[kb][0][2], b[kb][0][3],
                  su + offB[kb][0]);
            LDSM4(b[kb][1][0], b[kb][1][1], b[kb][1][2], b[kb][1][3],
                  su + offB[kb][1]);
        }

        #pragma unroll
        for (int kb = 0; kb < 4; kb++) {
            // scales for this quant block
            unsigned long long sxd[2][2];
            #pragma unroll
            for (int tm = 0; tm < 2; tm++)
                #pragma unroll
                for (int h = 0; h < 2; h++) {
                    float sx = *(const float*)(sxS + kb * 256 + sxBase +
                                               tm * 64 + h * 32);
                    sxd[tm][h] = pk2(sx, sx);
                }
            unsigned long long swp[4];
            #pragma unroll
            for (int tn = 0; tn < 4; tn++)
                swp[tn] = *(const unsigned long long*)(swS + kb * 256 +
                                                       swBase + tn * 32);

            #pragma unroll
            for (int tm = 0; tm < 2; tm++)
                #pragma unroll
                for (int g = 0; g < 2; g++) {
                    float p[4], q[4];
                    MMA_FP8_Z(p, a[kb][tm], b[kb][g][0], b[kb][g][2]);
                    MMA_FP8_Z(q, a[kb][tm], b[kb][g][1], b[kb][g][3]);
                    const int t0 = 2 * g, t1 = 2 * g + 1;
                    pfma2(acc2[tm][t0][0], pk2(p[0], p[1]),
                          pmul2(sxd[tm][0], swp[t0]));
                    pfma2(acc2[tm][t0][1], pk2(p[2], p[3]),
                          pmul2(sxd[tm][1], swp[t0]));
                    pfma2(acc2[tm][t1][0], pk2(q[0], q[1]),
                          pmul2(sxd[tm][0], swp[t1]));
                    pfma2(acc2[tm][t1][1], pk2(q[2], q[3]),
                          pmul2(sxd[tm][1], swp[t1]));
                }
        }
    }

    // epilogue: 8-byte packed stores
    #pragma unroll
    for (int tm = 0; tm < 2; tm++)
        #pragma unroll
        for (int h = 0; h < 2; h++) {
            int row = bm0 + m0 + tm * 16 + qrow + 8 * h;
            #pragma unroll
            for (int tn = 0; tn < 4; tn++) {
                unsigned long long v = acc2[tm][tn][h];
                *(unsigned long long*)(C + (size_t)row * N_DIM +
                                       bn0 + n0 + tn * 8 + qcol) = v;
            }
        }
}

// ---------------------------------------------------------------------------
extern "C" void kernel_launch(void* const* d_in, const int* in_sizes, int n_in,
                              void* d_out, int out_size) {
    (void)n_in; (void)in_sizes; (void)out_size;
    const float* x = (const float*)d_in[0];   // [M, K]
    const float* w = (const float*)d_in[1];   // [N, K]
    float* out = (float*)d_out;               // [M, N]

    uint8_t *qx = nullptr, *qw = nullptr;
    float *sx = nullptr, *sw = nullptr;
    cudaGetSymbolAddress((void**)&qx, g_qx);
    cudaGetSymbolAddress((void**)&qw, g_qw);
    cudaGetSymbolAddress((void**)&sx, g_sx);
    cudaGetSymbolAddress((void**)&sw, g_sw);

    // fused quant: x (1024 CTAs) + w (4096 CTAs) in one launch
    const int total_ctas = (int)(((M_DIM + N_DIM) * (size_t)K_DIM) / 16 / 256);
    quant_fused_kernel<<<total_ctas, 256>>>(x, w, qx, qw, sx, sw);

    cudaFuncSetAttribute(gemm_fp8,
                         cudaFuncAttributeMaxDynamicSharedMemorySize,
                         SMEM_TOTAL);
    dim3 grid(N_DIM / BN, M_DIM / BM);        // (64, 16) = 1024 CTAs
    gemm_fp8<<<grid, THREADS, SMEM_TOTAL>>>(qx, qw, sx, sw, out);
}